// round 14
// baseline (speedup 1.0000x reference)
#include <cuda_runtime.h>
#include <cuda_fp16.h>
#include <cstdint>

// Problem constants
constexpr int NB = 8;     // batch
constexpr int NC = 512;   // channels
constexpr int NW = 2048;  // width (sequence)
constexpr int NQ = 64;    // C/8 (qk head dim)
constexpr int NM = 2 * NQ + NC;  // 640 fused output channels

// Scratch (device globals; allocation-free per harness rules).
__device__ __align__(16) uint16_t g_wh[(size_t)NM * NC];         // W [m][c]
__device__ __align__(16) uint16_t g_xth[(size_t)NB * NW * NC];   // x^T [b][w][c]
__device__ __align__(16) uint16_t g_qkh[(size_t)NB * NW * 128];  // q|k [b][pos][ch]
__device__ __align__(16) uint16_t g_vh[(size_t)NB * NC * NW];    // v [b][c][j]
__device__ __align__(16) uint16_t g_ph[(size_t)NB * NW * NW];    // P unnorm [b][i][j]
__device__ __align__(16) float    g_mpart[(size_t)NB * NW * 4];  // partial row maxes
__device__ __align__(16) float    g_mrow[(size_t)NB * NW];       // final row maxes
__device__ __align__(16) float    g_spart[(size_t)NB * NW * 4];  // partial row sums

// ---------------- helpers ----------------------------------------------------

__device__ __forceinline__ uint32_t smem_u32(const void* p) {
    uint32_t a;
    asm("{ .reg .u64 t; cvta.to.shared.u64 t, %1; cvt.u32.u64 %0, t; }"
        : "=r"(a) : "l"(p));
    return a;
}

__device__ __forceinline__ uint32_t h2(float a, float b) {
    __half2 t = __floats2half2_rn(a, b);
    return *(uint32_t*)&t;
}
__device__ __forceinline__ unsigned short h1(float a) {
    __half t = __float2half_rn(a);
    return *(unsigned short*)&t;
}

#define LDSM_X4(R0, R1, R2, R3, A)                                            \
    asm volatile("ldmatrix.sync.aligned.m8n8.x4.shared.b16 {%0,%1,%2,%3}, [%4];" \
                 : "=r"(R0), "=r"(R1), "=r"(R2), "=r"(R3) : "r"(A))

#define MMA_F16(c, a, b)                                                      \
    asm volatile("mma.sync.aligned.m16n8k16.row.col.f32.f16.f16.f32 "         \
                 "{%0,%1,%2,%3}, {%4,%5,%6,%7}, {%8,%9}, {%0,%1,%2,%3};"      \
                 : "+f"((c)[0]), "+f"((c)[1]), "+f"((c)[2]), "+f"((c)[3])     \
                 : "r"((a)[0]), "r"((a)[1]), "r"((a)[2]), "r"((a)[3]),        \
                   "r"((b)[0]), "r"((b)[1]))

// K=32-chunk geometry: row = [32][8 pad] fp16 -> stride 40 el (80 B)
constexpr int SR32 = 40;
constexpr int T32  = 128 * SR32 * 2;     // 10240 B per operand tile
constexpr int ST32 = 2 * T32;            // 20480 B per stage
constexpr int GEMM_SMEM = 2 * ST32;      // 40960 B

// K=64 geometry: row = [64][8 pad] -> stride 72 el (144 B)
constexpr int SR64 = 72;
constexpr int T64  = 128 * SR64 * 2;     // 18432 B

// pmax smem layouts (byte offsets)
constexpr int PM_OFF_K   = T64;                       // sK double buffer
constexpr int PM_OFF_RED = PM_OFF_K + 2 * T64;        // float [4][128]
constexpr int PM_OFF_M   = PM_OFF_RED + 4 * 128 * 4;  // float [128]
constexpr int PM1_SMEM   = PM_OFF_M + 128 * 4;        // 57856 B
constexpr int SRP        = 136;
constexpr int PM_OFF_P   = PM_OFF_M + 128 * 4;        // sP [128][136]
constexpr int PM_OFF_S   = PM_OFF_P + 128 * SRP * 2;  // float [128]
constexpr int PM2_SMEM   = PM_OFF_S + 128 * 4;        // 93184 B

// ---------------- warp-tile 64x32 stage, fp16 single product ----------------

template <int SRA, int SRB, int NKS>
__device__ __forceinline__ void stage1(float acc[4][4][4], uint32_t aBase,
                                       uint32_t bBase, int wm, int wn,
                                       int lane) {
#pragma unroll
    for (int ks = 0; ks < NKS; ks++) {
        const int kb = ks * 16;
        uint32_t Ah[4][4], Bh[4][2];
        const int am = wm * 64 + (lane & 15);
        const int ak = kb + ((lane >> 4) << 3);
#pragma unroll
        for (int mf = 0; mf < 4; mf++) {
            uint32_t addr = aBase + ((am + mf * 16) * SRA + ak) * 2;
            LDSM_X4(Ah[mf][0], Ah[mf][1], Ah[mf][2], Ah[mf][3], addr);
        }
        const int bn = wn * 32 + ((lane >> 4) << 3) + (lane & 7);
        const int bk = kb + (((lane >> 3) & 1) << 3);
#pragma unroll
        for (int nfp = 0; nfp < 2; nfp++) {
            uint32_t addr = bBase + ((bn + nfp * 16) * SRB + bk) * 2;
            LDSM_X4(Bh[2 * nfp][0], Bh[2 * nfp][1],
                    Bh[2 * nfp + 1][0], Bh[2 * nfp + 1][1], addr);
        }
#pragma unroll
        for (int mf = 0; mf < 4; mf++)
#pragma unroll
            for (int nf = 0; nf < 4; nf++)
                MMA_F16(acc[mf][nf], Ah[mf], Bh[nf]);
    }
}

// ---------------- Kernel W: convert weights to fp16 -------------------------

__global__ void __launch_bounds__(128)
wprep_kernel(const float* __restrict__ Wq, const float* __restrict__ Wk,
             const float* __restrict__ Wv) {
    const int m = blockIdx.x;
    const float* src;
    if (m < NQ)            src = Wq + (size_t)m * NC;
    else if (m < 2 * NQ)   src = Wk + (size_t)(m - NQ) * NC;
    else                   src = Wv + (size_t)(m - 2 * NQ) * NC;
    const int c4 = threadIdx.x * 4;
    float4 v = *(const float4*)(src + c4);
    *(uint2*)(g_wh + (size_t)m * NC + c4) =
        make_uint2(h2(v.x, v.y), h2(v.z, v.w));
}

// ---------------- Kernel 0: transpose x -> [b][w][c] fp16 -------------------

__global__ void __launch_bounds__(256)
transpose_x_kernel(const float* __restrict__ x) {
    __shared__ float s[64][65];
    const int b  = blockIdx.z;
    const int c0 = blockIdx.y * 64;
    const int w0 = blockIdx.x * 64;
    const int tid = threadIdx.x;

#pragma unroll
    for (int it = 0; it < 4; it++) {
        int c  = it * 16 + (tid >> 4);
        int w4 = (tid & 15) * 4;
        float4 v =
            *(const float4*)(x + ((size_t)b * NC + c0 + c) * NW + w0 + w4);
        s[c][w4 + 0] = v.x; s[c][w4 + 1] = v.y;
        s[c][w4 + 2] = v.z; s[c][w4 + 3] = v.w;
    }
    __syncthreads();

#pragma unroll
    for (int it = 0; it < 4; it++) {
        int w  = it * 16 + (tid >> 4);
        int c4 = (tid & 15) * 4;
        float f0 = s[c4 + 0][w], f1 = s[c4 + 1][w];
        float f2 = s[c4 + 2][w], f3 = s[c4 + 3][w];
        size_t o = ((size_t)b * NW + w0 + w) * NC + c0 + c4;
        *(uint2*)(g_xth + o) = make_uint2(h2(f0, f1), h2(f2, f3));
    }
}

// ---------------- Kernel 1: QKV GEMM (fp16 1-product) -----------------------

__global__ void __launch_bounds__(256, 1)
qkv_mma_kernel(const float* __restrict__ bq, const float* __restrict__ bk,
               const float* __restrict__ bv) {
    extern __shared__ uint16_t smem[];
    const int b  = blockIdx.z;
    const int m0 = blockIdx.y * 128;
    const int w0 = blockIdx.x * 128;
    const int tid  = threadIdx.x;
    const int wid  = tid >> 5;
    const int lane = tid & 31;
    const int wm = wid >> 2, wn = wid & 3;

    const uint32_t sbase = smem_u32(smem);

    const int row = tid >> 1;
    const int c16 = (tid & 1) * 16;
    const uint16_t* rA = g_wh + (size_t)(m0 + row) * NC + c16;
    const uint16_t* rB = g_xth + ((size_t)b * NW + w0 + row) * NC + c16;

    float acc[4][4][4];
#pragma unroll
    for (int mf = 0; mf < 4; mf++)
#pragma unroll
        for (int nf = 0; nf < 4; nf++)
#pragma unroll
            for (int e = 0; e < 4; e++) acc[mf][nf][e] = 0.f;

    uint4 pa[2], pb[2];
#pragma unroll
    for (int q = 0; q < 2; q++) {
        pa[q] = *(const uint4*)(rA + 8 * q);
        pb[q] = *(const uint4*)(rB + 8 * q);
    }

    constexpr int NCH = NC / 32;   // 16
#pragma unroll 1
    for (int chunk = 0; chunk < NCH; chunk++) {
        const int p = chunk & 1;
        uint16_t* sA = smem + p * (ST32 / 2);
        uint16_t* sB = sA + T32 / 2;
#pragma unroll
        for (int q = 0; q < 2; q++) {
            *(uint4*)(sA + row * SR32 + c16 + 8 * q) = pa[q];
            *(uint4*)(sB + row * SR32 + c16 + 8 * q) = pb[q];
        }
        __syncthreads();

        if (chunk < NCH - 1) {
            const int kk = (chunk + 1) * 32;
#pragma unroll
            for (int q = 0; q < 2; q++) {
                pa[q] = *(const uint4*)(rA + kk + 8 * q);
                pb[q] = *(const uint4*)(rB + kk + 8 * q);
            }
        }

        const uint32_t aBase = sbase + p * ST32;
        stage1<SR32, SR32, 2>(acc, aBase, aBase + T32, wm, wn, lane);
    }

#pragma unroll
    for (int mf = 0; mf < 4; mf++) {
#pragma unroll
        for (int half = 0; half < 2; half++) {
            const int m = m0 + wm * 64 + mf * 16 + (lane >> 2) + 8 * half;
            if (m0 == 0 && m < 128) {
                const float bias = (m < NQ) ? bq[m] : bk[m - NQ];
#pragma unroll
                for (int nf = 0; nf < 4; nf++) {
                    const int n = w0 + wn * 32 + nf * 8 + ((lane & 3) << 1);
                    float y0 = acc[mf][nf][2 * half + 0] + bias;
                    float y1 = acc[mf][nf][2 * half + 1] + bias;
                    size_t o0 = ((size_t)b * NW + n) * 128 + m;
                    g_qkh[o0]       = h1(y0);
                    g_qkh[o0 + 128] = h1(y1);
                }
            } else if (m0 > 0) {
                const int c = m - 128;
                const float bias = bv[c];
#pragma unroll
                for (int nf = 0; nf < 4; nf++) {
                    const int n = w0 + wn * 32 + nf * 8 + ((lane & 3) << 1);
                    float y0 = acc[mf][nf][2 * half + 0] + bias;
                    float y1 = acc[mf][nf][2 * half + 1] + bias;
                    *(uint32_t*)(g_vh + ((size_t)b * NC + c) * NW + n) = h2(y0, y1);
                }
            }
        }
    }
}

// ---------------- Kernel 2a: pmax1 — partial row maxes over j-slab ----------
// grid (i-tile, jsplit, b); each CTA: S for 128 i x 512 j, row-max -> g_mpart.

__global__ void __launch_bounds__(256, 2)
pmax1_kernel() {
    extern __shared__ uint16_t smem[];
    const int b  = blockIdx.z;
    const int i0 = blockIdx.x * 128;
    const int js = blockIdx.y;
    const int tid  = threadIdx.x;
    const int lane = tid & 31;
    const int wid  = tid >> 5;
    const int wm = wid >> 2, wn = wid & 3;

    const uint32_t sbase = smem_u32(smem);
    uint16_t* sQ = smem;
    float* sRed = (float*)(smem + PM_OFF_RED / 2);
    float* sM   = (float*)(smem + PM_OFF_M / 2);

    const int row = tid >> 1;
    const int h32 = (tid & 1) * 32;
    {
        const uint16_t* qh = g_qkh + ((size_t)b * NW + i0 + row) * 128 + h32;
#pragma unroll
        for (int q = 0; q < 4; q++)
            *(uint4*)(sQ + row * SR64 + h32 + 8 * q) = *(const uint4*)(qh + 8 * q);
    }
    if (tid < 128) sM[tid] = -1e30f;
    __syncthreads();

    const uint16_t* kptr =
        g_qkh + ((size_t)b * NW + js * 512 + row) * 128 + 64 + h32;
    constexpr size_t KSTRIDE = (size_t)128 * 128;

    uint4 pk[4];
#pragma unroll
    for (int q = 0; q < 4; q++) pk[q] = *(const uint4*)(kptr + 8 * q);

#pragma unroll 1
    for (int jt = 0; jt < 4; jt++) {
        uint16_t* sK = smem + (T64 + (jt & 1) * T64) / 2;
#pragma unroll
        for (int q = 0; q < 4; q++)
            *(uint4*)(sK + row * SR64 + h32 + 8 * q) = pk[q];
        __syncthreads();
        if (jt < 3) {
#pragma unroll
            for (int q = 0; q < 4; q++)
                pk[q] = *(const uint4*)(kptr + (jt + 1) * KSTRIDE + 8 * q);
        }

        float S[4][4][4];
#pragma unroll
        for (int mf = 0; mf < 4; mf++)
#pragma unroll
            for (int nf = 0; nf < 4; nf++)
#pragma unroll
                for (int e = 0; e < 4; e++) S[mf][nf][e] = 0.f;
        stage1<SR64, SR64, 4>(S, sbase, sbase + T64 + (jt & 1) * T64,
                              wm, wn, lane);

#pragma unroll
        for (int mf = 0; mf < 4; mf++)
#pragma unroll
            for (int e = 0; e < 2; e++) {
                const int r = wm * 64 + mf * 16 + (lane >> 2) + 8 * e;
                float v = S[mf][0][2 * e];
#pragma unroll
                for (int nf = 0; nf < 4; nf++) {
                    v = fmaxf(v, S[mf][nf][2 * e]);
                    v = fmaxf(v, S[mf][nf][2 * e + 1]);
                }
                v = fmaxf(v, __shfl_xor_sync(0xffffffffu, v, 1));
                v = fmaxf(v, __shfl_xor_sync(0xffffffffu, v, 2));
                if ((lane & 3) == 0) sRed[wn * 128 + r] = v;
            }
        __syncthreads();
        if (tid < 128) {
            float m = fmaxf(fmaxf(sRed[tid], sRed[128 + tid]),
                            fmaxf(sRed[256 + tid], sRed[384 + tid]));
            sM[tid] = fmaxf(sM[tid], m);
        }
        __syncthreads();
    }

    if (tid < 128)
        g_mpart[((size_t)b * NW + i0 + tid) * 4 + js] = sM[tid];
}

// ---------------- Kernel 2b: reduce partial maxes ---------------------------

__global__ void __launch_bounds__(256)
maxred_kernel() {
    const size_t r = (size_t)blockIdx.x * 256 + threadIdx.x;
    float4 m4 = *(const float4*)(g_mpart + r * 4);
    g_mrow[r] = fmaxf(fmaxf(m4.x, m4.y), fmaxf(m4.z, m4.w));
}

// ---------------- Kernel 2c: pmax2 — P = exp(S - m), partial sums -----------

__global__ void __launch_bounds__(256, 2)
pmax2_kernel() {
    extern __shared__ uint16_t smem[];
    const int b  = blockIdx.z;
    const int i0 = blockIdx.x * 128;
    const int js = blockIdx.y;
    const int tid  = threadIdx.x;
    const int lane = tid & 31;
    const int wid  = tid >> 5;
    const int wm = wid >> 2, wn = wid & 3;

    const uint32_t sbase = smem_u32(smem);
    uint16_t* sQ = smem;
    float* sRed = (float*)(smem + PM_OFF_RED / 2);
    float* sM   = (float*)(smem + PM_OFF_M / 2);
    uint16_t* sP = smem + PM_OFF_P / 2;
    float* sS   = (float*)(smem + PM_OFF_S / 2);

    const int row = tid >> 1;
    const int h32 = (tid & 1) * 32;
    {
        const uint16_t* qh = g_qkh + ((size_t)b * NW + i0 + row) * 128 + h32;
#pragma unroll
        for (int q = 0; q < 4; q++)
            *(uint4*)(sQ + row * SR64 + h32 + 8 * q) = *(const uint4*)(qh + 8 * q);
    }
    if (tid < 128) {
        sM[tid] = g_mrow[(size_t)b * NW + i0 + tid];
        sS[tid] = 0.f;
    }
    __syncthreads();

    const uint16_t* kptr =
        g_qkh + ((size_t)b * NW + js * 512 + row) * 128 + 64 + h32;
    constexpr size_t KSTRIDE = (size_t)128 * 128;

    uint4 pk[4];
#pragma unroll
    for (int q = 0; q < 4; q++) pk[q] = *(const uint4*)(kptr + 8 * q);

#pragma unroll 1
    for (int jt = 0; jt < 4; jt++) {
        uint16_t* sK = smem + (T64 + (jt & 1) * T64) / 2;
#pragma unroll
        for (int q = 0; q < 4; q++)
            *(uint4*)(sK + row * SR64 + h32 + 8 * q) = pk[q];
        __syncthreads();
        if (jt < 3) {
#pragma unroll
            for (int q = 0; q < 4; q++)
                pk[q] = *(const uint4*)(kptr + (jt + 1) * KSTRIDE + 8 * q);
        }

        float S[4][4][4];
#pragma unroll
        for (int mf = 0; mf < 4; mf++)
#pragma unroll
            for (int nf = 0; nf < 4; nf++)
#pragma unroll
                for (int e = 0; e < 4; e++) S[mf][nf][e] = 0.f;
        stage1<SR64, SR64, 4>(S, sbase, sbase + T64 + (jt & 1) * T64,
                              wm, wn, lane);

#pragma unroll
        for (int mf = 0; mf < 4; mf++)
#pragma unroll
            for (int e = 0; e < 2; e++) {
                const int r = wm * 64 + mf * 16 + (lane >> 2) + 8 * e;
                const float mr = sM[r];
                float ssum = 0.f;
#pragma unroll
                for (int nf = 0; nf < 4; nf++) {
                    float p0 = __expf(S[mf][nf][2 * e + 0] - mr);
                    float p1 = __expf(S[mf][nf][2 * e + 1] - mr);
                    ssum += p0 + p1;
                    const int col = wn * 32 + nf * 8 + ((lane & 3) << 1);
                    *(uint32_t*)(sP + r * SRP + col) = h2(p0, p1);
                }
                ssum += __shfl_xor_sync(0xffffffffu, ssum, 1);
                ssum += __shfl_xor_sync(0xffffffffu, ssum, 2);
                if ((lane & 3) == 0) sRed[wn * 128 + r] = ssum;
            }
        __syncthreads();
        if (tid < 128)
            sS[tid] += sRed[tid] + sRed[128 + tid] +
                       sRed[256 + tid] + sRed[384 + tid];
        {
            const int r2 = tid >> 1;
            const int hh = (tid & 1) * 64;
            uint16_t* dst = g_ph + ((size_t)b * NW + i0 + r2) * NW +
                            js * 512 + jt * 128 + hh;
#pragma unroll
            for (int q = 0; q < 8; q++)
                *(uint4*)(dst + 8 * q) = *(uint4*)(sP + r2 * SRP + hh + 8 * q);
        }
        __syncthreads();
    }

    if (tid < 128)
        g_spart[((size_t)b * NW + i0 + tid) * 4 + js] = sS[tid];
}

// ---------------- Kernel 4: out GEMM (fp16 1-product, /s in epilogue) -------

__global__ void __launch_bounds__(256, 1)
out_mma_kernel(const float* __restrict__ x, const float* __restrict__ gamma,
               float* __restrict__ out) {
    extern __shared__ uint16_t smem[];
    const int b  = blockIdx.z;
    const int c0 = blockIdx.x * 128;
    const int i0 = blockIdx.y * 128;
    const int tid  = threadIdx.x;
    const int wid  = tid >> 5;
    const int lane = tid & 31;
    const int wm = wid >> 2, wn = wid & 3;

    const uint32_t sbase = smem_u32(smem);

    const int row = tid >> 1;
    const int c16 = (tid & 1) * 16;
    const uint16_t* rA = g_vh + ((size_t)b * NC + c0 + row) * NW + c16;
    const uint16_t* rB = g_ph + ((size_t)b * NW + i0 + row) * NW + c16;

    float acc[4][4][4];
#pragma unroll
    for (int mf = 0; mf < 4; mf++)
#pragma unroll
        for (int nf = 0; nf < 4; nf++)
#pragma unroll
            for (int e = 0; e < 4; e++) acc[mf][nf][e] = 0.f;

    uint4 pa[2], pb[2];
#pragma unroll
    for (int q = 0; q < 2; q++) {
        pa[q] = *(const uint4*)(rA + 8 * q);
        pb[q] = *(const uint4*)(rB + 8 * q);
    }

    constexpr int NCH = NW / 32;   // 64
#pragma unroll 1
    for (int chunk = 0; chunk < NCH; chunk++) {
        const int p = chunk & 1;
        uint16_t* sA = smem + p * (ST32 / 2);
        uint16_t* sB = sA + T32 / 2;
#pragma unroll
        for (int q = 0; q < 2; q++) {
            *(uint4*)(sA + row * SR32 + c16 + 8 * q) = pa[q];
            *(uint4*)(sB + row * SR32 + c16 + 8 * q) = pb[q];
        }
        __syncthreads();

        if (chunk < NCH - 1) {
            const int kk = (chunk + 1) * 32;
#pragma unroll
            for (int q = 0; q < 2; q++) {
                pa[q] = *(const uint4*)(rA + kk + 8 * q);
                pb[q] = *(const uint4*)(rB + kk + 8 * q);
            }
        }

        const uint32_t aBase = sbase + p * ST32;
        stage1<SR32, SR32, 2>(acc, aBase, aBase + T32, wm, wn, lane);
    }

    const float gam = gamma[0];
    float iv0[4], iv1[4];
#pragma unroll
    for (int nf = 0; nf < 4; nf++) {
        const int n = i0 + wn * 32 + nf * 8 + ((lane & 3) << 1);
        float4 s0 = *(const float4*)(g_spart + ((size_t)b * NW + n) * 4);
        float4 s1 = *(const float4*)(g_spart + ((size_t)b * NW + n + 1) * 4);
        iv0[nf] = gam / (s0.x + s0.y + s0.z + s0.w);
        iv1[nf] = gam / (s1.x + s1.y + s1.z + s1.w);
    }
#pragma unroll
    for (int mf = 0; mf < 4; mf++) {
        const int m = c0 + wm * 64 + mf * 16 + (lane >> 2);
#pragma unroll
        for (int nf = 0; nf < 4; nf++) {
            const int n = i0 + wn * 32 + nf * 8 + ((lane & 3) << 1);
            size_t o0 = ((size_t)b * NC + m) * NW + n;
            float2 xv0 = *(const float2*)(x + o0);
            *(float2*)(out + o0) =
                make_float2(fmaf(acc[mf][nf][0], iv0[nf], xv0.x),
                            fmaf(acc[mf][nf][1], iv1[nf], xv0.y));
            size_t o1 = o0 + (size_t)8 * NW;
            float2 xv1 = *(const float2*)(x + o1);
            *(float2*)(out + o1) =
                make_float2(fmaf(acc[mf][nf][2], iv0[nf], xv1.x),
                            fmaf(acc[mf][nf][3], iv1[nf], xv1.y));
        }
    }
}

// ---------------- launch ----------------------------------------------------

extern "C" void kernel_launch(void* const* d_in, const int* in_sizes, int n_in,
                              void* d_out, int out_size) {
    const float* x     = (const float*)d_in[0];
    const float* Wq    = (const float*)d_in[1];
    const float* bq    = (const float*)d_in[2];
    const float* Wk    = (const float*)d_in[3];
    const float* bk    = (const float*)d_in[4];
    const float* Wv    = (const float*)d_in[5];
    const float* bv    = (const float*)d_in[6];
    const float* gamma = (const float*)d_in[7];
    float* out = (float*)d_out;

    cudaFuncSetAttribute(qkv_mma_kernel,
                         cudaFuncAttributeMaxDynamicSharedMemorySize, GEMM_SMEM);
    cudaFuncSetAttribute(pmax1_kernel,
                         cudaFuncAttributeMaxDynamicSharedMemorySize, PM1_SMEM);
    cudaFuncSetAttribute(pmax2_kernel,
                         cudaFuncAttributeMaxDynamicSharedMemorySize, PM2_SMEM);
    cudaFuncSetAttribute(out_mma_kernel,
                         cudaFuncAttributeMaxDynamicSharedMemorySize, GEMM_SMEM);

    wprep_kernel<<<NM, 128>>>(Wq, Wk, Wv);
    transpose_x_kernel<<<dim3(NW / 64, NC / 64, NB), 256>>>(x);
    qkv_mma_kernel<<<dim3(NW / 128, 5, NB), 256, GEMM_SMEM>>>(bq, bk, bv);
    pmax1_kernel<<<dim3(NW / 128, 4, NB), 256, PM1_SMEM>>>();
    maxred_kernel<<<NB * NW / 256, 256>>>();
    pmax2_kernel<<<dim3(NW / 128, 4, NB), 256, PM2_SMEM>>>();
    out_mma_kernel<<<dim3(NC / 128, NW / 128, NB), 256, GEMM_SMEM>>>(x, gamma, out);
}

// round 15
// speedup vs baseline: 1.4043x; 1.4043x over previous
#include <cuda_runtime.h>
#include <cuda_fp16.h>
#include <cstdint>

// Problem constants
constexpr int NB = 8;     // batch
constexpr int NC = 512;   // channels
constexpr int NW = 2048;  // width (sequence)
constexpr int NQ = 64;    // C/8 (qk head dim)
constexpr int NM = 2 * NQ + NC;  // 640 fused output channels

// Scratch (device globals; allocation-free per harness rules).
__device__ __align__(16) uint16_t g_wh[(size_t)NM * NC];         // W [m][c]
__device__ __align__(16) uint16_t g_xth[(size_t)NB * NW * NC];   // x^T [b][w][c]
__device__ __align__(16) uint16_t g_qkh[(size_t)NB * NW * 128];  // q|k [b][pos][ch]
__device__ __align__(16) uint16_t g_vh[(size_t)NB * NC * NW];    // v [b][c][j]
__device__ __align__(16) uint16_t g_ph[(size_t)NB * NW * NW];    // P unnorm [b][i][j]
__device__ __align__(16) float    g_srow[(size_t)NB * NW];       // softmax row sums

// ---------------- helpers ----------------------------------------------------

__device__ __forceinline__ uint32_t smem_u32(const void* p) {
    uint32_t a;
    asm("{ .reg .u64 t; cvta.to.shared.u64 t, %1; cvt.u32.u64 %0, t; }"
        : "=r"(a) : "l"(p));
    return a;
}

__device__ __forceinline__ uint32_t h2(float a, float b) {
    __half2 t = __floats2half2_rn(a, b);
    return *(uint32_t*)&t;
}
__device__ __forceinline__ unsigned short h1(float a) {
    __half t = __float2half_rn(a);
    return *(unsigned short*)&t;
}

#define LDSM_X4(R0, R1, R2, R3, A)                                            \
    asm volatile("ldmatrix.sync.aligned.m8n8.x4.shared.b16 {%0,%1,%2,%3}, [%4];" \
                 : "=r"(R0), "=r"(R1), "=r"(R2), "=r"(R3) : "r"(A))

#define MMA_F16(c, a, b)                                                      \
    asm volatile("mma.sync.aligned.m16n8k16.row.col.f32.f16.f16.f32 "         \
                 "{%0,%1,%2,%3}, {%4,%5,%6,%7}, {%8,%9}, {%0,%1,%2,%3};"      \
                 : "+f"((c)[0]), "+f"((c)[1]), "+f"((c)[2]), "+f"((c)[3])     \
                 : "r"((a)[0]), "r"((a)[1]), "r"((a)[2]), "r"((a)[3]),        \
                   "r"((b)[0]), "r"((b)[1]))

#define CP_ASYNC16(smem, gptr)                                                \
    asm volatile("cp.async.cg.shared.global [%0], [%1], 16;"                  \
                 :: "r"(smem), "l"(gptr))
#define CP_COMMIT() asm volatile("cp.async.commit_group;" ::: "memory")
#define CP_WAIT1()  asm volatile("cp.async.wait_group 1;" ::: "memory")
#define CP_WAIT0()  asm volatile("cp.async.wait_group 0;" ::: "memory")

// K=32-chunk geometry: row = [32][8 pad] fp16 -> stride 40 el (80 B)
constexpr int SR32 = 40;
constexpr int T32  = 128 * SR32 * 2;     // 10240 B per operand tile
constexpr int ST32 = 2 * T32;            // 20480 B per stage
constexpr int GEMM_SMEM = 3 * ST32;      // 61440 B, 3-stage cp.async

// K=64 geometry: row = [64][8 pad] -> stride 72 el (144 B)
constexpr int SR64 = 72;
constexpr int T64  = 128 * SR64 * 2;     // 18432 B

// pmax smem layout (byte offsets; smem declared as uint16_t*)
constexpr int PM_OFF_K   = T64;                    // sK double buffer 2x18432
constexpr int PM_OFF_P   = PM_OFF_K + 2 * T64;     // sP [128][136]
constexpr int SRP        = 136;
constexpr int PM_OFF_RED = PM_OFF_P + 128 * SRP * 2;  // float [4][128]
constexpr int PM_OFF_M   = PM_OFF_RED + 4 * 128 * 4;  // float [128]
constexpr int PM_OFF_S   = PM_OFF_M + 128 * 4;        // float [128]
constexpr int PM_SMEM    = PM_OFF_S + 128 * 4;        // 93184 B

// ---------------- warp-tile 64x32 stage, fp16 single product ----------------

template <int SRA, int SRB, int NKS>
__device__ __forceinline__ void stage1(float acc[4][4][4], uint32_t aBase,
                                       uint32_t bBase, int wm, int wn,
                                       int lane) {
#pragma unroll
    for (int ks = 0; ks < NKS; ks++) {
        const int kb = ks * 16;
        uint32_t Ah[4][4], Bh[4][2];
        const int am = wm * 64 + (lane & 15);
        const int ak = kb + ((lane >> 4) << 3);
#pragma unroll
        for (int mf = 0; mf < 4; mf++) {
            uint32_t addr = aBase + ((am + mf * 16) * SRA + ak) * 2;
            LDSM_X4(Ah[mf][0], Ah[mf][1], Ah[mf][2], Ah[mf][3], addr);
        }
        const int bn = wn * 32 + ((lane >> 4) << 3) + (lane & 7);
        const int bk = kb + (((lane >> 3) & 1) << 3);
#pragma unroll
        for (int nfp = 0; nfp < 2; nfp++) {
            uint32_t addr = bBase + ((bn + nfp * 16) * SRB + bk) * 2;
            LDSM_X4(Bh[2 * nfp][0], Bh[2 * nfp][1],
                    Bh[2 * nfp + 1][0], Bh[2 * nfp + 1][1], addr);
        }
#pragma unroll
        for (int mf = 0; mf < 4; mf++)
#pragma unroll
            for (int nf = 0; nf < 4; nf++)
                MMA_F16(acc[mf][nf], Ah[mf], Bh[nf]);
    }
}

// ---------------- Kernel W: convert weights to fp16 -------------------------

__global__ void __launch_bounds__(128)
wprep_kernel(const float* __restrict__ Wq, const float* __restrict__ Wk,
             const float* __restrict__ Wv) {
    const int m = blockIdx.x;
    const float* src;
    if (m < NQ)            src = Wq + (size_t)m * NC;
    else if (m < 2 * NQ)   src = Wk + (size_t)(m - NQ) * NC;
    else                   src = Wv + (size_t)(m - 2 * NQ) * NC;
    const int c4 = threadIdx.x * 4;
    float4 v = *(const float4*)(src + c4);
    *(uint2*)(g_wh + (size_t)m * NC + c4) =
        make_uint2(h2(v.x, v.y), h2(v.z, v.w));
}

// ---------------- Kernel 0: transpose x -> [b][w][c] fp16 -------------------

__global__ void __launch_bounds__(256)
transpose_x_kernel(const float* __restrict__ x) {
    __shared__ float s[64][65];
    const int b  = blockIdx.z;
    const int c0 = blockIdx.y * 64;
    const int w0 = blockIdx.x * 64;
    const int tid = threadIdx.x;

#pragma unroll
    for (int it = 0; it < 4; it++) {
        int c  = it * 16 + (tid >> 4);
        int w4 = (tid & 15) * 4;
        float4 v =
            *(const float4*)(x + ((size_t)b * NC + c0 + c) * NW + w0 + w4);
        s[c][w4 + 0] = v.x; s[c][w4 + 1] = v.y;
        s[c][w4 + 2] = v.z; s[c][w4 + 3] = v.w;
    }
    __syncthreads();

#pragma unroll
    for (int it = 0; it < 4; it++) {
        int w  = it * 16 + (tid >> 4);
        int c4 = (tid & 15) * 4;
        float f0 = s[c4 + 0][w], f1 = s[c4 + 1][w];
        float f2 = s[c4 + 2][w], f3 = s[c4 + 3][w];
        size_t o = ((size_t)b * NW + w0 + w) * NC + c0 + c4;
        *(uint2*)(g_xth + o) = make_uint2(h2(f0, f1), h2(f2, f3));
    }
}

// ---------------- Kernel 1: QKV GEMM (fp16 1-product, cp.async 3-stage) -----

__global__ void __launch_bounds__(256)
qkv_mma_kernel(const float* __restrict__ bq, const float* __restrict__ bk,
               const float* __restrict__ bv) {
    extern __shared__ uint16_t smem[];
    const int b  = blockIdx.z;
    const int m0 = blockIdx.y * 128;
    const int w0 = blockIdx.x * 128;
    const int tid  = threadIdx.x;
    const int wid  = tid >> 5;
    const int lane = tid & 31;
    const int wm = wid >> 2, wn = wid & 3;

    const uint32_t sbase = smem_u32(smem);

    const int row = tid >> 1;
    const int c16 = (tid & 1) * 16;
    const uint16_t* rA = g_wh + (size_t)(m0 + row) * NC + c16;
    const uint16_t* rB = g_xth + ((size_t)b * NW + w0 + row) * NC + c16;
    const uint32_t sOffA = (uint32_t)(row * SR32 + c16) * 2;

    float acc[4][4][4];
#pragma unroll
    for (int mf = 0; mf < 4; mf++)
#pragma unroll
        for (int nf = 0; nf < 4; nf++)
#pragma unroll
            for (int e = 0; e < 4; e++) acc[mf][nf][e] = 0.f;

    constexpr int NCH = NC / 32;   // 16

#define QKV_ISSUE(i)                                                          \
    do {                                                                      \
        const uint32_t st = sbase + ((i) % 3) * ST32;                         \
        const int kk = (i) * 32;                                              \
        CP_ASYNC16(st + sOffA,            rA + kk);                           \
        CP_ASYNC16(st + sOffA + 16,       rA + kk + 8);                       \
        CP_ASYNC16(st + T32 + sOffA,      rB + kk);                           \
        CP_ASYNC16(st + T32 + sOffA + 16, rB + kk + 8);                       \
        CP_COMMIT();                                                          \
    } while (0)

    QKV_ISSUE(0);
    QKV_ISSUE(1);
#pragma unroll 1
    for (int i = 0; i < NCH; i++) {
        if (i < NCH - 1) { CP_WAIT1(); } else { CP_WAIT0(); }
        __syncthreads();
        if (i + 2 < NCH) QKV_ISSUE(i + 2);
        const uint32_t aBase = sbase + (i % 3) * ST32;
        stage1<SR32, SR32, 2>(acc, aBase, aBase + T32, wm, wn, lane);
    }
#undef QKV_ISSUE

#pragma unroll
    for (int mf = 0; mf < 4; mf++) {
#pragma unroll
        for (int half = 0; half < 2; half++) {
            const int m = m0 + wm * 64 + mf * 16 + (lane >> 2) + 8 * half;
            if (m0 == 0 && m < 128) {
                const float bias = (m < NQ) ? bq[m] : bk[m - NQ];
#pragma unroll
                for (int nf = 0; nf < 4; nf++) {
                    const int n = w0 + wn * 32 + nf * 8 + ((lane & 3) << 1);
                    float y0 = acc[mf][nf][2 * half + 0] + bias;
                    float y1 = acc[mf][nf][2 * half + 1] + bias;
                    size_t o0 = ((size_t)b * NW + n) * 128 + m;
                    g_qkh[o0]       = h1(y0);
                    g_qkh[o0 + 128] = h1(y1);
                }
            } else if (m0 > 0) {
                const int c = m - 128;
                const float bias = bv[c];
#pragma unroll
                for (int nf = 0; nf < 4; nf++) {
                    const int n = w0 + wn * 32 + nf * 8 + ((lane & 3) << 1);
                    float y0 = acc[mf][nf][2 * half + 0] + bias;
                    float y1 = acc[mf][nf][2 * half + 1] + bias;
                    *(uint32_t*)(g_vh + ((size_t)b * NC + c) * NW + n) = h2(y0, y1);
                }
            }
        }
    }
}

// ---------------- Kernel 2: pmax — fused energy + softmax (R13) -------------

__global__ void __launch_bounds__(256, 1)
pmax_kernel() {
    extern __shared__ uint16_t smem[];
    const int b  = blockIdx.y;
    const int i0 = blockIdx.x * 128;
    const int tid  = threadIdx.x;
    const int lane = tid & 31;
    const int wid  = tid >> 5;
    const int wm = wid >> 2, wn = wid & 3;

    const uint32_t sbase = smem_u32(smem);
    uint16_t* sQ = smem;
    float* sRed = (float*)(smem + PM_OFF_RED / 2);
    float* sM   = (float*)(smem + PM_OFF_M / 2);
    float* sS   = (float*)(smem + PM_OFF_S / 2);
    uint16_t* sP = smem + PM_OFF_P / 2;

    const int row = tid >> 1;
    const int h32 = (tid & 1) * 32;

    {
        const uint16_t* qh = g_qkh + ((size_t)b * NW + i0 + row) * 128 + h32;
#pragma unroll
        for (int q = 0; q < 4; q++)
            *(uint4*)(sQ + row * SR64 + h32 + 8 * q) = *(const uint4*)(qh + 8 * q);
    }
    if (tid < 128) { sM[tid] = -1e30f; sS[tid] = 0.f; }
    __syncthreads();

    const uint16_t* kptr = g_qkh + ((size_t)b * NW + row) * 128 + 64 + h32;
    constexpr size_t KSTRIDE = (size_t)128 * 128;

    // phase 1: row max
    {
        uint4 pk[4];
#pragma unroll
        for (int q = 0; q < 4; q++) pk[q] = *(const uint4*)(kptr + 8 * q);

#pragma unroll 1
        for (int jt = 0; jt < 16; jt++) {
            uint16_t* sK = smem + (T64 + (jt & 1) * T64) / 2;
#pragma unroll
            for (int q = 0; q < 4; q++)
                *(uint4*)(sK + row * SR64 + h32 + 8 * q) = pk[q];
            __syncthreads();
            if (jt < 15) {
#pragma unroll
                for (int q = 0; q < 4; q++)
                    pk[q] = *(const uint4*)(kptr + (jt + 1) * KSTRIDE + 8 * q);
            }

            float S[4][4][4];
#pragma unroll
            for (int mf = 0; mf < 4; mf++)
#pragma unroll
                for (int nf = 0; nf < 4; nf++)
#pragma unroll
                    for (int e = 0; e < 4; e++) S[mf][nf][e] = 0.f;
            stage1<SR64, SR64, 4>(S, sbase, sbase + T64 + (jt & 1) * T64,
                                  wm, wn, lane);

#pragma unroll
            for (int mf = 0; mf < 4; mf++)
#pragma unroll
                for (int e = 0; e < 2; e++) {
                    const int r = wm * 64 + mf * 16 + (lane >> 2) + 8 * e;
                    float v = S[mf][0][2 * e];
#pragma unroll
                    for (int nf = 0; nf < 4; nf++) {
                        v = fmaxf(v, S[mf][nf][2 * e]);
                        v = fmaxf(v, S[mf][nf][2 * e + 1]);
                    }
                    v = fmaxf(v, __shfl_xor_sync(0xffffffffu, v, 1));
                    v = fmaxf(v, __shfl_xor_sync(0xffffffffu, v, 2));
                    if ((lane & 3) == 0) sRed[wn * 128 + r] = v;
                }
            __syncthreads();
            if (tid < 128) {
                float m = fmaxf(fmaxf(sRed[tid], sRed[128 + tid]),
                                fmaxf(sRed[256 + tid], sRed[384 + tid]));
                sM[tid] = fmaxf(sM[tid], m);
            }
            __syncthreads();
        }
    }

    // phase 2: P = exp(S - m), sums, store
    {
        uint4 pk[4];
#pragma unroll
        for (int q = 0; q < 4; q++) pk[q] = *(const uint4*)(kptr + 8 * q);

#pragma unroll 1
        for (int jt = 0; jt < 16; jt++) {
            uint16_t* sK = smem + (T64 + (jt & 1) * T64) / 2;
#pragma unroll
            for (int q = 0; q < 4; q++)
                *(uint4*)(sK + row * SR64 + h32 + 8 * q) = pk[q];
            __syncthreads();
            if (jt < 15) {
#pragma unroll
                for (int q = 0; q < 4; q++)
                    pk[q] = *(const uint4*)(kptr + (jt + 1) * KSTRIDE + 8 * q);
            }

            float S[4][4][4];
#pragma unroll
            for (int mf = 0; mf < 4; mf++)
#pragma unroll
                for (int nf = 0; nf < 4; nf++)
#pragma unroll
                    for (int e = 0; e < 4; e++) S[mf][nf][e] = 0.f;
            stage1<SR64, SR64, 4>(S, sbase, sbase + T64 + (jt & 1) * T64,
                                  wm, wn, lane);

#pragma unroll
            for (int mf = 0; mf < 4; mf++)
#pragma unroll
                for (int e = 0; e < 2; e++) {
                    const int r = wm * 64 + mf * 16 + (lane >> 2) + 8 * e;
                    const float mr = sM[r];
                    float ssum = 0.f;
#pragma unroll
                    for (int nf = 0; nf < 4; nf++) {
                        float p0 = __expf(S[mf][nf][2 * e + 0] - mr);
                        float p1 = __expf(S[mf][nf][2 * e + 1] - mr);
                        ssum += p0 + p1;
                        const int col = wn * 32 + nf * 8 + ((lane & 3) << 1);
                        *(uint32_t*)(sP + r * SRP + col) = h2(p0, p1);
                    }
                    ssum += __shfl_xor_sync(0xffffffffu, ssum, 1);
                    ssum += __shfl_xor_sync(0xffffffffu, ssum, 2);
                    if ((lane & 3) == 0) sRed[wn * 128 + r] = ssum;
                }
            __syncthreads();
            if (tid < 128)
                sS[tid] += sRed[tid] + sRed[128 + tid] +
                           sRed[256 + tid] + sRed[384 + tid];
            {
                const int r2 = tid >> 1;
                const int hh = (tid & 1) * 64;
                uint16_t* dst = g_ph + ((size_t)b * NW + i0 + r2) * NW + jt * 128 + hh;
#pragma unroll
                for (int q = 0; q < 8; q++)
                    *(uint4*)(dst + 8 * q) = *(uint4*)(sP + r2 * SRP + hh + 8 * q);
            }
            __syncthreads();
        }
    }

    if (tid < 128) g_srow[(size_t)b * NW + i0 + tid] = sS[tid];
}

// ---------------- Kernel 4: out GEMM (fp16 1-product, cp.async 3-stage) -----
// out[c,i] = gamma/s[i] * sum_j v[c,j] P[i,j] + x[c,i].

__global__ void __launch_bounds__(256)
out_mma_kernel(const float* __restrict__ x, const float* __restrict__ gamma,
               float* __restrict__ out) {
    extern __shared__ uint16_t smem[];
    const int b  = blockIdx.z;
    const int c0 = blockIdx.x * 128;
    const int i0 = blockIdx.y * 128;
    const int tid  = threadIdx.x;
    const int wid  = tid >> 5;
    const int lane = tid & 31;
    const int wm = wid >> 2, wn = wid & 3;

    const uint32_t sbase = smem_u32(smem);

    const int row = tid >> 1;
    const int c16 = (tid & 1) * 16;
    const uint16_t* rA = g_vh + ((size_t)b * NC + c0 + row) * NW + c16;
    const uint16_t* rB = g_ph + ((size_t)b * NW + i0 + row) * NW + c16;
    const uint32_t sOffA = (uint32_t)(row * SR32 + c16) * 2;

    float acc[4][4][4];
#pragma unroll
    for (int mf = 0; mf < 4; mf++)
#pragma unroll
        for (int nf = 0; nf < 4; nf++)
#pragma unroll
            for (int e = 0; e < 4; e++) acc[mf][nf][e] = 0.f;

    constexpr int NCH = NW / 32;   // 64

#define OUT_ISSUE(i)                                                          \
    do {                                                                      \
        const uint32_t st = sbase + ((i) % 3) * ST32;                         \
        const int kk = (i) * 32;                                              \
        CP_ASYNC16(st + sOffA,            rA + kk);                           \
        CP_ASYNC16(st + sOffA + 16,       rA + kk + 8);                       \
        CP_ASYNC16(st + T32 + sOffA,      rB + kk);                           \
        CP_ASYNC16(st + T32 + sOffA + 16, rB + kk + 8);                       \
        CP_COMMIT();                                                          \
    } while (0)

    OUT_ISSUE(0);
    OUT_ISSUE(1);
#pragma unroll 1
    for (int i = 0; i < NCH; i++) {
        if (i < NCH - 1) { CP_WAIT1(); } else { CP_WAIT0(); }
        __syncthreads();
        if (i + 2 < NCH) OUT_ISSUE(i + 2);
        const uint32_t aBase = sbase + (i % 3) * ST32;
        stage1<SR32, SR32, 2>(acc, aBase, aBase + T32, wm, wn, lane);
    }
#undef OUT_ISSUE

    const float gam = gamma[0];
    float iv0[4], iv1[4];
#pragma unroll
    for (int nf = 0; nf < 4; nf++) {
        const int n = i0 + wn * 32 + nf * 8 + ((lane & 3) << 1);
        float2 sv = *(const float2*)(g_srow + (size_t)b * NW + n);
        iv0[nf] = gam / sv.x;
        iv1[nf] = gam / sv.y;
    }
#pragma unroll
    for (int mf = 0; mf < 4; mf++) {
        const int m = c0 + wm * 64 + mf * 16 + (lane >> 2);
#pragma unroll
        for (int nf = 0; nf < 4; nf++) {
            const int n = i0 + wn * 32 + nf * 8 + ((lane & 3) << 1);
            size_t o0 = ((size_t)b * NC + m) * NW + n;
            float2 xv0 = *(const float2*)(x + o0);
            *(float2*)(out + o0) =
                make_float2(fmaf(acc[mf][nf][0], iv0[nf], xv0.x),
                            fmaf(acc[mf][nf][1], iv1[nf], xv0.y));
            size_t o1 = o0 + (size_t)8 * NW;
            float2 xv1 = *(const float2*)(x + o1);
            *(float2*)(out + o1) =
                make_float2(fmaf(acc[mf][nf][2], iv0[nf], xv1.x),
                            fmaf(acc[mf][nf][3], iv1[nf], xv1.y));
        }
    }
}

// ---------------- launch ----------------------------------------------------

extern "C" void kernel_launch(void* const* d_in, const int* in_sizes, int n_in,
                              void* d_out, int out_size) {
    const float* x     = (const float*)d_in[0];
    const float* Wq    = (const float*)d_in[1];
    const float* bq    = (const float*)d_in[2];
    const float* Wk    = (const float*)d_in[3];
    const float* bk    = (const float*)d_in[4];
    const float* Wv    = (const float*)d_in[5];
    const float* bv    = (const float*)d_in[6];
    const float* gamma = (const float*)d_in[7];
    float* out = (float*)d_out;

    cudaFuncSetAttribute(qkv_mma_kernel,
                         cudaFuncAttributeMaxDynamicSharedMemorySize, GEMM_SMEM);
    cudaFuncSetAttribute(pmax_kernel,
                         cudaFuncAttributeMaxDynamicSharedMemorySize, PM_SMEM);
    cudaFuncSetAttribute(out_mma_kernel,
                         cudaFuncAttributeMaxDynamicSharedMemorySize, GEMM_SMEM);

    wprep_kernel<<<NM, 128>>>(Wq, Wk, Wv);
    transpose_x_kernel<<<dim3(NW / 64, NC / 64, NB), 256>>>(x);
    qkv_mma_kernel<<<dim3(NW / 128, 5, NB), 256, GEMM_SMEM>>>(bq, bk, bv);
    pmax_kernel<<<dim3(NW / 128, NB), 256, PM_SMEM>>>();
    out_mma_kernel<<<dim3(NC / 128, NW / 128, NB), 256, GEMM_SMEM>>>(x, gamma, out);
}